// round 15
// baseline (speedup 1.0000x reference)
#include <cuda_runtime.h>
#include <math.h>

#define TPB_B   256               // build block
#define TPB_P   128               // process block
#define JN      128
#define MP      128
#define GRID    32                // 32x32 cells of size 0.25 over [-4,4]
#define NCELL   (GRID * GRID)
#define CCAP    128
#define CAP     4096              // per-patch segment capacity (max real ~1300)
#define SQCAP   1536              // smem queue per build block (expected ~655)
#define EPB     128               // entries per block-pass (64 pairs x 2 entries)
#define CHY     11                // process y-blocks per patch (11*128 = 1408 slots)

// scratch: static __device__ arrays (zero-initialized at module load)
__device__ int    g_cellCnt[NCELL];
__device__ int    g_cellList[NCELL * CCAP];
__device__ int    g_cnt[MP];
__device__ int    g_idx[MP * CAP];
__device__ float2 g_std[MP * CAP];

__device__ __forceinline__ int cell_clamp(int i) { return min(GRID - 1, max(0, i)); }
__device__ __forceinline__ int cell_of(float v) {
    return cell_clamp((int)floorf((v + 4.0f) * 4.0f));
}
__device__ __forceinline__ float frcp(float x) {
    float r; asm("rcp.approx.f32 %0, %1;" : "=f"(r) : "f"(x)); return r;
}
__device__ __forceinline__ float fex2(float x) {
    float r; asm("ex2.approx.f32 %0, %1;" : "=f"(r) : "f"(x)); return r;
}

// ---------------------------------------------------------------------------
// bin (measured 4.4us): WARP-PER-CELL. 64 blocks x 512 = 1024 warps.
// Ballot + popc-prefix writes the compacted candidate list cooperatively.
// Margin 1e-5 kills fp edge false-negatives; edge cells extend outward for
// clamped points; exact |d|<=0.25 in build decides membership. Resets g_cnt.
// ---------------------------------------------------------------------------
__global__ void __launch_bounds__(512)
rf_bin_kernel(const float2* __restrict__ cs2)
{
    __shared__ float2 scs[MP];
    for (int i = threadIdx.x; i < MP; i += 512) scs[i] = cs2[i];
    __syncthreads();

    const int wid  = threadIdx.x >> 5;
    const int lane = threadIdx.x & 31;
    const int cell = blockIdx.x * 16 + wid;            // 0..1023
    if (blockIdx.x == 0 && threadIdx.x < MP) g_cnt[threadIdx.x] = 0;

    const int ix = cell & (GRID - 1);
    const int iy = cell >> 5;
    const float x0 = -4.0f + 0.25f * ix, x1 = x0 + 0.25f;
    const float y0 = -4.0f + 0.25f * iy, y1 = y0 + 0.25f;
    const float R = 0.25001f;

    int* list = g_cellList + cell * CCAP;
    int base = 0;
    #pragma unroll
    for (int r = 0; r < MP / 32; r++) {
        const int m = r * 32 + lane;
        const float2 c = scs[m];
        const bool ovx = (c.x - R <= x1 || ix == GRID - 1) &&
                         (c.x + R >= x0 || ix == 0);
        const bool ovy = (c.y - R <= y1 || iy == GRID - 1) &&
                         (c.y + R >= y0 || iy == 0);
        const bool cand = ovx && ovy;
        const unsigned mask = __ballot_sync(0xFFFFFFFFu, cand);
        if (cand) list[base + __popc(mask & ((1u << lane) - 1))] = m;
        base += __popc(mask);
    }
    if (lane == 0) g_cellCnt[cell] = base;
}

// ---------------------------------------------------------------------------
// build (measured ~5.2us): 128 blocks x 256. Candidate scan via cell list,
// warp-aggregated smem queue, histogram -> one 128-wide global reservation
// wave -> cursor scatter into contiguous per-patch segments.
// |p-c| <= 0.25  <=>  |std| <= 1 exactly (x4 exact in fp32).
// ---------------------------------------------------------------------------
__global__ void __launch_bounds__(TPB_B)
rf_build_kernel(const float2* __restrict__ p2, const float2* __restrict__ cs2,
                float* __restrict__ out, int N)
{
    __shared__ float2 scs[MP];
    __shared__ int    scnt[MP];
    __shared__ int    sbase[MP];
    __shared__ int    sqpos;
    __shared__ int    qmn[SQCAP];     // (m << 16) | n
    __shared__ float2 qs[SQCAP];

    const int tid  = threadIdx.x;
    const int lane = tid & 31;

    for (int i = tid; i < MP; i += TPB_B) { scs[i] = cs2[i]; scnt[i] = 0; }
    if (tid == 0) sqpos = 0;
    __syncthreads();

    const int n = blockIdx.x * TPB_B + tid;
    float2 pv = make_float2(1e30f, 1e30f);
    int cell = 0, k = 0;
    if (n < N) {
        out[n] = 0.0f;                 // zero output (process runs later)
        pv = p2[n];
        cell = (cell_of(pv.y) << 5) | cell_of(pv.x);
        k = g_cellCnt[cell];
    }
    const int kmax = __reduce_max_sync(0xFFFFFFFFu, k);

    for (int t = 0; t < kmax; t++) {
        const bool cand = (t < k);
        const int  m = cand ? g_cellList[cell * CCAP + t] : 0;
        const float2 c = scs[m];
        const float d0 = pv.x - c.x;
        const float d1 = pv.y - c.y;
        const bool hit = cand && (fabsf(d0) <= 0.25f) && (fabsf(d1) <= 0.25f);
        const unsigned mask = __ballot_sync(0xFFFFFFFFu, hit);
        if (mask) {
            const int cnt    = __popc(mask);
            const int leader = __ffs(mask) - 1;
            int wq = 0;
            if (lane == leader) wq = atomicAdd(&sqpos, cnt);
            wq = __shfl_sync(0xFFFFFFFFu, wq, leader);
            if (hit) {
                const int pos = wq + __popc(mask & ((1u << lane) - 1));
                if (pos < SQCAP) {
                    qmn[pos] = (m << 16) | n;
                    qs[pos]  = make_float2(d0 * 4.0f, d1 * 4.0f);
                }
            }
        }
    }
    __syncthreads();
    const int qtot = min(sqpos, SQCAP);

    for (int i = tid; i < qtot; i += TPB_B)
        atomicAdd(&scnt[qmn[i] >> 16], 1);
    __syncthreads();

    if (tid < MP) sbase[tid] = atomicAdd(&g_cnt[tid], scnt[tid]);
    __syncthreads();

    for (int i = tid; i < qtot; i += TPB_B) {
        const int key = qmn[i];
        const int m   = key >> 16;
        const int g   = atomicAdd(&sbase[m], 1);
        if (g < CAP) {
            const int at = m * CAP + g;
            g_idx[at] = key & 0xFFFF;
            g_std[at] = qs[i];
        }
    }
}

// ---------------------------------------------------------------------------
// process: split-j x ILP2. Lane pair (2k,2k+1) owns TWO entries (A at
// q+pair, B at q+64+pair); each lane computes 64 of the 128 j's for both.
// Every coefficient LDS.128 now feeds 4 j-evals (2 entries x 2 j) -> issue
// slots per j-eval ~0.24 vs 0.37. Coefficients prescaled by K = 2*log2(e):
// tanh(a) = fma(-2, rcp(ex2(a')+1), 1) — 1 EX2 + 1 RCP, clean saturation,
// ~1e-7 rel. Clamped loads + masked atomics handle the tail; ballot-gated
// uniform loop keeps the shfl legal.
// ---------------------------------------------------------------------------
__global__ void __launch_bounds__(TPB_P)
rf_process_kernel(const float* __restrict__ W, const float* __restrict__ b,
                  const float* __restrict__ um, float* __restrict__ out)
{
    const int m   = blockIdx.x;
    const int cnt = min(g_cnt[m], CAP);
    if (cnt <= blockIdx.y * EPB) return;          // uniform per block

    __shared__ float4 sC[JN];
    const float K = 2.8853900817779268f;          // 2*log2(e)
    for (int j = threadIdx.x; j < JN; j += TPB_P) {
        sC[j] = make_float4(W[m * (2 * JN) + j] * K,
                            W[m * (2 * JN) + JN + j] * K,
                            b[m * JN + j] * K,
                            um[m * JN + j]);
    }
    __syncthreads();

    const int*    segN = g_idx + m * CAP;
    const float2* segS = g_std + m * CAP;
    const int jbase = (threadIdx.x & 1) * (JN / 2);   // 0 or 64
    const int pair  = threadIdx.x >> 1;               // 0..63

    int q = blockIdx.y * EPB;
    while (__ballot_sync(0xFFFFFFFFu, q + pair < cnt)) {
        const int iA = q + pair;
        const int iB = q + 64 + pair;
        const bool vA = (iA < cnt);
        const bool vB = (iB < cnt);
        const int sA_i = vA ? iA : 0;
        const int sB_i = vB ? iB : 0;
        const int nA = segN[sA_i];
        const int nB = segN[sB_i];
        float2 sA = segS[sA_i];
        float2 sB = segS[sB_i];
        if (!vA) sA = make_float2(0.f, 0.f);
        if (!vB) sB = make_float2(0.f, 0.f);

        float accA0 = 0.f, accA1 = 0.f, accB0 = 0.f, accB1 = 0.f;
        #pragma unroll 8
        for (int jj = 0; jj < JN / 2; jj += 2) {
            const float4 ca = sC[jbase + jj];
            const float4 cb = sC[jbase + jj + 1];
            float aA0 = fmaf(sA.x, ca.x, fmaf(sA.y, ca.y, ca.z));
            float aA1 = fmaf(sA.x, cb.x, fmaf(sA.y, cb.y, cb.z));
            float aB0 = fmaf(sB.x, ca.x, fmaf(sB.y, ca.y, ca.z));
            float aB1 = fmaf(sB.x, cb.x, fmaf(sB.y, cb.y, cb.z));
            float rA0 = frcp(fex2(aA0) + 1.0f);
            float rA1 = frcp(fex2(aA1) + 1.0f);
            float rB0 = frcp(fex2(aB0) + 1.0f);
            float rB1 = frcp(fex2(aB1) + 1.0f);
            accA0 = fmaf(fmaf(-2.0f, rA0, 1.0f), ca.w, accA0);
            accA1 = fmaf(fmaf(-2.0f, rA1, 1.0f), cb.w, accA1);
            accB0 = fmaf(fmaf(-2.0f, rB0, 1.0f), ca.w, accB0);
            accB1 = fmaf(fmaf(-2.0f, rB1, 1.0f), cb.w, accB1);
        }
        float accA = accA0 + accA1;
        float accB = accB0 + accB1;
        accA += __shfl_xor_sync(0xFFFFFFFFu, accA, 1);   // combine j-halves
        accB += __shfl_xor_sync(0xFFFFFFFFu, accB, 1);
        if (!(threadIdx.x & 1)) {
            if (vA) atomicAdd(&out[nA], accA);
            if (vB) atomicAdd(&out[nB], accB);
        }
        q += EPB * CHY;
    }
}

// ---------------------------------------------------------------------------
// inputs (metadata order): p[N,2] f32, cs[128,2] f32, W[128,2,128] f32,
//                          b[128,128] f32, um[128,128] f32 ; out [N,1] f32
// ---------------------------------------------------------------------------
extern "C" void kernel_launch(void* const* d_in, const int* in_sizes, int n_in,
                              void* d_out, int out_size)
{
    const float* p  = (const float*)d_in[0];
    const float* cs = (const float*)d_in[1];
    const float* W  = (const float*)d_in[2];
    const float* b  = (const float*)d_in[3];
    const float* um = (const float*)d_in[4];
    float* out = (float*)d_out;

    const int N = in_sizes[0] / 2;   // 32768

    rf_bin_kernel<<<64, 512>>>((const float2*)cs);

    rf_build_kernel<<<(N + TPB_B - 1) / TPB_B, TPB_B>>>(
        (const float2*)p, (const float2*)cs, out, N);

    dim3 pgrid(MP, CHY);
    rf_process_kernel<<<pgrid, TPB_P>>>(W, b, um, out);
}

// round 17
// speedup vs baseline: 1.1664x; 1.1664x over previous
#include <cuda_runtime.h>
#include <math.h>

#define TPB_B   256               // build block
#define TPB_P   256               // process block
#define JN      128
#define MP      128
#define GRID    32                // 32x32 cells of size 0.25 over [-4,4]
#define NCELL   (GRID * GRID)
#define CCAP    128
#define CAP     4096              // per-patch segment capacity (max real ~1300)
#define SQCAP   1536              // smem queue per build block (expected ~655)
#define CHY     11                // process y-blocks per patch
#define EPB     (TPB_P / 2)       // entries per pass (split-j: 2 threads/entry)

// scratch: static __device__ arrays (zero-initialized at module load)
__device__ int    g_cellCnt[NCELL];
__device__ int    g_cellList[NCELL * CCAP];
__device__ int    g_cnt[MP];
__device__ int    g_idx[MP * CAP];
__device__ float2 g_std[MP * CAP];

__device__ __forceinline__ int cell_clamp(int i) { return min(GRID - 1, max(0, i)); }
__device__ __forceinline__ int cell_of(float v) {
    return cell_clamp((int)floorf((v + 4.0f) * 4.0f));
}
__device__ __forceinline__ float frcp(float x) {
    float r; asm("rcp.approx.f32 %0, %1;" : "=f"(r) : "f"(x)); return r;
}
__device__ __forceinline__ float fex2(float x) {
    float r; asm("ex2.approx.f32 %0, %1;" : "=f"(r) : "f"(x)); return r;
}

// ---------------------------------------------------------------------------
// bin (R11, measured 4.4us): WARP-PER-CELL. 64 blocks x 512 = 1024 warps.
// Ballot + popc-prefix writes the compacted candidate list cooperatively.
// Margin 1e-5 kills fp edge false-negatives; edge cells extend outward for
// clamped points; exact |d|<=0.25 in build decides membership. Resets g_cnt.
// ---------------------------------------------------------------------------
__global__ void __launch_bounds__(512)
rf_bin_kernel(const float2* __restrict__ cs2)
{
    __shared__ float2 scs[MP];
    for (int i = threadIdx.x; i < MP; i += 512) scs[i] = cs2[i];
    __syncthreads();

    const int wid  = threadIdx.x >> 5;
    const int lane = threadIdx.x & 31;
    const int cell = blockIdx.x * 16 + wid;            // 0..1023
    if (blockIdx.x == 0 && threadIdx.x < MP) g_cnt[threadIdx.x] = 0;

    const int ix = cell & (GRID - 1);
    const int iy = cell >> 5;
    const float x0 = -4.0f + 0.25f * ix, x1 = x0 + 0.25f;
    const float y0 = -4.0f + 0.25f * iy, y1 = y0 + 0.25f;
    const float R = 0.25001f;

    int* list = g_cellList + cell * CCAP;
    int base = 0;
    #pragma unroll
    for (int r = 0; r < MP / 32; r++) {
        const int m = r * 32 + lane;
        const float2 c = scs[m];
        const bool ovx = (c.x - R <= x1 || ix == GRID - 1) &&
                         (c.x + R >= x0 || ix == 0);
        const bool ovy = (c.y - R <= y1 || iy == GRID - 1) &&
                         (c.y + R >= y0 || iy == 0);
        const bool cand = ovx && ovy;
        const unsigned mask = __ballot_sync(0xFFFFFFFFu, cand);
        if (cand) list[base + __popc(mask & ((1u << lane) - 1))] = m;
        base += __popc(mask);
    }
    if (lane == 0) g_cellCnt[cell] = base;
}

// ---------------------------------------------------------------------------
// build (R11, measured ~5.2us): 128 blocks x 256. Candidate scan via cell
// list, warp-aggregated smem queue, histogram -> one 128-wide global
// reservation wave -> cursor scatter into contiguous per-patch segments.
// |p-c| <= 0.25  <=>  |std| <= 1 exactly (x4 exact in fp32).
// ---------------------------------------------------------------------------
__global__ void __launch_bounds__(TPB_B)
rf_build_kernel(const float2* __restrict__ p2, const float2* __restrict__ cs2,
                float* __restrict__ out, int N)
{
    __shared__ float2 scs[MP];
    __shared__ int    scnt[MP];
    __shared__ int    sbase[MP];
    __shared__ int    sqpos;
    __shared__ int    qmn[SQCAP];     // (m << 16) | n
    __shared__ float2 qs[SQCAP];

    const int tid  = threadIdx.x;
    const int lane = tid & 31;

    for (int i = tid; i < MP; i += TPB_B) { scs[i] = cs2[i]; scnt[i] = 0; }
    if (tid == 0) sqpos = 0;
    __syncthreads();

    const int n = blockIdx.x * TPB_B + tid;
    float2 pv = make_float2(1e30f, 1e30f);
    int cell = 0, k = 0;
    if (n < N) {
        out[n] = 0.0f;                 // zero output (process runs later)
        pv = p2[n];
        cell = (cell_of(pv.y) << 5) | cell_of(pv.x);
        k = g_cellCnt[cell];
    }
    const int kmax = __reduce_max_sync(0xFFFFFFFFu, k);

    for (int t = 0; t < kmax; t++) {
        const bool cand = (t < k);
        const int  m = cand ? g_cellList[cell * CCAP + t] : 0;
        const float2 c = scs[m];
        const float d0 = pv.x - c.x;
        const float d1 = pv.y - c.y;
        const bool hit = cand && (fabsf(d0) <= 0.25f) && (fabsf(d1) <= 0.25f);
        const unsigned mask = __ballot_sync(0xFFFFFFFFu, hit);
        if (mask) {
            const int cnt    = __popc(mask);
            const int leader = __ffs(mask) - 1;
            int wq = 0;
            if (lane == leader) wq = atomicAdd(&sqpos, cnt);
            wq = __shfl_sync(0xFFFFFFFFu, wq, leader);
            if (hit) {
                const int pos = wq + __popc(mask & ((1u << lane) - 1));
                if (pos < SQCAP) {
                    qmn[pos] = (m << 16) | n;
                    qs[pos]  = make_float2(d0 * 4.0f, d1 * 4.0f);
                }
            }
        }
    }
    __syncthreads();
    const int qtot = min(sqpos, SQCAP);

    for (int i = tid; i < qtot; i += TPB_B)
        atomicAdd(&scnt[qmn[i] >> 16], 1);
    __syncthreads();

    if (tid < MP) sbase[tid] = atomicAdd(&g_cnt[tid], scnt[tid]);
    __syncthreads();

    for (int i = tid; i < qtot; i += TPB_B) {
        const int key = qmn[i];
        const int m   = key >> 16;
        const int g   = atomicAdd(&sbase[m], 1);
        if (g < CAP) {
            const int at = m * CAP + g;
            g_idx[at] = key & 0xFFFF;
            g_std[at] = qs[i];
        }
    }
}

// ---------------------------------------------------------------------------
// process: R11 split-j structure (2 threads/entry, 64 j's each, one shfl_xor
// combine, ballot-gated uniform loop) with ONE change: K = 2*log2(e)
// prescaled coefficients + paired reciprocal. Per j-pair: 2 EX2 + 1 RCP
// (1.5 MUFU/j vs 2) and fewer issue slots. tanh(a) = 1 - 2/(2^{a'}+1);
// r = rcp(x0*x1), 1/x0 = x1*r, 1/x1 = x0*r. Saturates cleanly; inf-product
// needs |arg|>40 where tanh==+-1 — unreachable on real data. ~2e-7 rel.
// ---------------------------------------------------------------------------
__global__ void __launch_bounds__(TPB_P)
rf_process_kernel(const float* __restrict__ W, const float* __restrict__ b,
                  const float* __restrict__ um, float* __restrict__ out)
{
    const int m   = blockIdx.x;
    const int cnt = min(g_cnt[m], CAP);
    if (cnt <= blockIdx.y * EPB) return;          // uniform per block

    __shared__ float4 sC[JN];
    const float K = 2.8853900817779268f;          // 2*log2(e)
    for (int j = threadIdx.x; j < JN; j += TPB_P) {
        sC[j] = make_float4(W[m * (2 * JN) + j] * K,
                            W[m * (2 * JN) + JN + j] * K,
                            b[m * JN + j] * K,
                            um[m * JN + j]);
    }
    __syncthreads();

    const int*    segN = g_idx + m * CAP;
    const float2* segS = g_std + m * CAP;
    const int jbase = (threadIdx.x & 1) * (JN / 2);

    int i = blockIdx.y * EPB + (threadIdx.x >> 1);
    while (__ballot_sync(0xFFFFFFFFu, i < cnt)) {
        const bool valid = (i < cnt);
        int    n = 0;
        float2 s = make_float2(0.0f, 0.0f);
        if (valid) { n = segN[i]; s = segS[i]; }

        float acc0 = 0.0f, acc1 = 0.0f;
        #pragma unroll 8
        for (int jj = 0; jj < JN / 2; jj += 2) {
            const float4 ca = sC[jbase + jj];
            const float4 cb = sC[jbase + jj + 1];
            float a0 = fmaf(s.x, ca.x, fmaf(s.y, ca.y, ca.z));
            float a1 = fmaf(s.x, cb.x, fmaf(s.y, cb.y, cb.z));
            float x0 = fex2(a0) + 1.0f;
            float x1 = fex2(a1) + 1.0f;
            float r  = frcp(x0 * x1);
            float u0 = x1 * r;            // = 1/x0
            float u1 = x0 * r;            // = 1/x1
            float t0 = fmaf(-2.0f, u0, 1.0f);
            float t1 = fmaf(-2.0f, u1, 1.0f);
            acc0 = fmaf(t0, ca.w, acc0);
            acc1 = fmaf(t1, cb.w, acc1);
        }
        float acc = acc0 + acc1;
        acc += __shfl_xor_sync(0xFFFFFFFFu, acc, 1);  // combine j-halves
        if (valid && !(threadIdx.x & 1)) atomicAdd(&out[n], acc);
        i += EPB * CHY;
    }
}

// ---------------------------------------------------------------------------
// inputs (metadata order): p[N,2] f32, cs[128,2] f32, W[128,2,128] f32,
//                          b[128,128] f32, um[128,128] f32 ; out [N,1] f32
// ---------------------------------------------------------------------------
extern "C" void kernel_launch(void* const* d_in, const int* in_sizes, int n_in,
                              void* d_out, int out_size)
{
    const float* p  = (const float*)d_in[0];
    const float* cs = (const float*)d_in[1];
    const float* W  = (const float*)d_in[2];
    const float* b  = (const float*)d_in[3];
    const float* um = (const float*)d_in[4];
    float* out = (float*)d_out;

    const int N = in_sizes[0] / 2;   // 32768

    rf_bin_kernel<<<64, 512>>>((const float2*)cs);

    rf_build_kernel<<<(N + TPB_B - 1) / TPB_B, TPB_B>>>(
        (const float2*)p, (const float2*)cs, out, N);

    dim3 pgrid(MP, CHY);
    rf_process_kernel<<<pgrid, TPB_P>>>(W, b, um, out);
}